// round 1
// baseline (speedup 1.0000x reference)
#include <cuda_runtime.h>
#include <math.h>

#define BSZ  16
#define N    512
#define TILE 64
#define HALO 11
#define RG   (TILE + 2*HALO)   /* 86 */
#define RP   (RG + 2)          /* 88: smem pitch */
#define HID  32
#define NPTS (BSZ*N*N)
#define SMEM_BYTES (3*RG*RP*4) /* 90816 B: x ping, x pong, f */

__device__ float  g_x0[NPTS];
__device__ float  g_x1[NPTS];
__device__ double g_acc[2];

__global__ void zero_acc_kernel() {
    if (threadIdx.x < 2) g_acc[threadIdx.x] = 0.0;
}

__device__ __forceinline__ float gelu_fast(float v) {
    // jax.nn.gelu approximate=True: 0.5*v*(1+tanh(sqrt(2/pi)*(v+0.044715 v^3)))
    float t = 0.7978845608028654f * fmaf(0.044715f * v * v, v, v);
    float th;
    asm("tanh.approx.f32 %0, %1;" : "=f"(th) : "f"(t));
    return 0.5f * v * (1.0f + th);
}

__global__ void __launch_bounds__(256, 2)
iter_kernel(int dir, int zero_in,
            const float* __restrict__ f,  const float* __restrict__ kA,
            const float* __restrict__ W1, const float* __restrict__ b1g,
            const float* __restrict__ W2, const float* __restrict__ b2g)
{
    const float* xin  = dir ? g_x1 : g_x0;
    float*       xout = dir ? g_x0 : g_x1;

    extern __shared__ float sm[];
    float* xsA = sm;
    float* xsB = sm + RG*RP;
    float* fs  = sm + 2*RG*RP;

    __shared__ float sW1[2*HID], sb1[HID], sW2[HID], sb2;

    const int b   = blockIdx.z;
    const int tid = threadIdx.y * 32 + threadIdx.x;
    const int gx0v = blockIdx.x * TILE - HALO;
    const int gy0v = blockIdx.y * TILE - HALO;

    const float* kb = kA + b * 9;
    const float k00 = __ldg(kb+0), k01 = __ldg(kb+1), k02 = __ldg(kb+2);
    const float k10 = __ldg(kb+3), k11 = __ldg(kb+4), k12 = __ldg(kb+5);
    const float k20 = __ldg(kb+6), k21 = __ldg(kb+7), k22 = __ldg(kb+8);
    const float tau = 0.5f / k11;

    if (tid < 2*HID)      sW1[tid]     = W1[tid];
    else if (tid < 96)    sb1[tid-64]  = b1g[tid-64];
    else if (tid < 128)   sW2[tid-96]  = W2[tid-96];
    else if (tid == 128)  sb2          = b2g[0];

    // ---- cooperative region load (x and f, zero-padded outside domain) ----
    const float* fb = f   + b * N * N;
    const float* xb = xin + b * N * N;
    for (int idx = tid; idx < RG*RG; idx += 256) {
        int ly = idx / RG;
        int lx = idx - ly * RG;
        int gy = gy0v + ly, gx = gx0v + lx;
        float xv = 0.f, fv = 0.f;
        if ((unsigned)gx < N && (unsigned)gy < N) {
            int gi = gy * N + gx;
            fv = fb[gi];
            if (!zero_in) xv = xb[gi];
        }
        xsA[ly*RP + lx] = xv;
        fs [ly*RP + lx] = fv;
    }
    __syncthreads();

    // ---- 10 Jacobi sweeps, shrinking halo, register sliding window ----
    float* cur = xsA;
    float* nxt = xsB;
    #pragma unroll 1
    for (int s = 0; s < 10; ++s) {
        const int lo = s + 1, hi = RG - 1 - s;
        const int span  = hi - lo;
        const int chunk = (span + 7) >> 3;
        const int ys = lo + (int)threadIdx.y * chunk;
        const int ye = min(hi, ys + chunk);
        for (int cx = lo + (int)threadIdx.x; cx < hi; cx += 32) {
            if (ys < ye) {
                const bool okx = (unsigned)(gx0v + cx) < N;
                float t0 = cur[(ys-1)*RP + cx - 1], t1 = cur[(ys-1)*RP + cx], t2 = cur[(ys-1)*RP + cx + 1];
                float m0 = cur[ ys   *RP + cx - 1], m1 = cur[ ys   *RP + cx], m2 = cur[ ys   *RP + cx + 1];
                for (int y = ys; y < ye; ++y) {
                    float n0 = cur[(y+1)*RP + cx - 1], n1 = cur[(y+1)*RP + cx], n2 = cur[(y+1)*RP + cx + 1];
                    float ax = k00*t0 + k01*t1 + k02*t2
                             + k10*m0 + k11*m1 + k12*m2
                             + k20*n0 + k21*n1 + k22*n2;
                    float xn = fmaf(tau, fs[y*RP + cx] - ax, m1);
                    bool ok = okx && ((unsigned)(gy0v + y) < N);
                    nxt[y*RP + cx] = ok ? xn : 0.f;
                    t0 = m0; t1 = m1; t2 = m2;
                    m0 = n0; m1 = n1; m2 = n2;
                }
            }
        }
        __syncthreads();
        float* tb = cur; cur = nxt; nxt = tb;
    }
    // cur == xsA again: x after 10 sweeps, valid on [10,76)^2

    // ---- residual + LFA + pointwise MLP + global write on interior ----
    const float w2pih = 6.28318530717958647692f / 513.0f;
    const float cA = k00 + k22, cB = k02 + k20, cC = k01 + k21, cD = k10 + k12;
    const float sA = k22 - k00, sB = k02 - k20, sC = k21 - k01, sD = k12 - k10;
    float* xo = xout + b * N * N;

    for (int cxl = threadIdx.x; cxl < TILE; cxl += 32) {
        const int cx = HALO + cxl;
        const int gx = gx0v + cx;
        float s1, c1;
        __sincosf(w2pih * (float)(gx - 256), &s1, &c1);

        const int ys = HALO + (int)threadIdx.y * (TILE/8);
        float t0 = cur[(ys-1)*RP + cx - 1], t1 = cur[(ys-1)*RP + cx], t2 = cur[(ys-1)*RP + cx + 1];
        float m0 = cur[ ys   *RP + cx - 1], m1 = cur[ ys   *RP + cx], m2 = cur[ ys   *RP + cx + 1];
        #pragma unroll 1
        for (int y = ys; y < ys + TILE/8; ++y) {
            float n0 = cur[(y+1)*RP + cx - 1], n1 = cur[(y+1)*RP + cx], n2 = cur[(y+1)*RP + cx + 1];
            float ax = k00*t0 + k01*t1 + k02*t2
                     + k10*m0 + k11*m1 + k12*m2
                     + k20*n0 + k21*n1 + k22*n2;
            float r = fs[y*RP + cx] - ax;

            const int gy = gy0v + y;
            float s2, c2;
            __sincosf(w2pih * (float)(gy - 256), &s2, &c2);
            float cc = c1*c2, ssv = s1*s2, sc = s1*c2, cs = c1*s2;
            float cpp = cc - ssv, spp = sc + cs;   // cos/sin(th1+th2)
            float cpm = cc + ssv, spm = sc - cs;   // cos/sin(th1-th2)
            float ReS = cA*cpp + cB*cpm + cC*c2 + cD*c1 + k11;
            float ImS = sA*spp + sB*spm + sC*s2 + sD*s1;
            float Re = 1.f - tau * ReS;
            float Im = -tau * ImS;
            float mg2 = Re*Re + Im*Im;
            float lfa = mg2 * mg2 * sqrtf(mg2);    // |1-tau*S|^5

            float acc = sb2;
            #pragma unroll 8
            for (int j = 0; j < HID; ++j) {
                float v = fmaf(sW1[2*j], lfa, fmaf(sW1[2*j+1], r, sb1[j]));
                acc = fmaf(sW2[j], gelu_fast(v), acc);
            }
            xo[gy*N + gx] = m1 + acc;

            t0 = m0; t1 = m1; t2 = m2;
            m0 = n0; m1 = n1; m2 = n2;
        }
    }
}

__global__ void __launch_bounds__(256)
reduce_kernel(const float* __restrict__ f, const float* __restrict__ kA)
{
    __shared__ float xt[(TILE+2)*(TILE+4)];   // 66 x 68 pitch
    __shared__ float redbuf[16];
    const int b   = blockIdx.z;
    const int tid = threadIdx.y*32 + threadIdx.x;
    const float* xb = g_x1 + b*N*N;           // final x lives in g_x1
    const float* fb = f    + b*N*N;
    const int gx0v = blockIdx.x*TILE - 1;
    const int gy0v = blockIdx.y*TILE - 1;

    for (int idx = tid; idx < 66*66; idx += 256) {
        int ly = idx / 66, lx = idx - ly*66;
        int gy = gy0v + ly, gx = gx0v + lx;
        xt[ly*68 + lx] = ((unsigned)gx < N && (unsigned)gy < N) ? xb[gy*N + gx] : 0.f;
    }
    const float* kb = kA + b * 9;
    const float k00 = __ldg(kb+0), k01 = __ldg(kb+1), k02 = __ldg(kb+2);
    const float k10 = __ldg(kb+3), k11 = __ldg(kb+4), k12 = __ldg(kb+5);
    const float k20 = __ldg(kb+6), k21 = __ldg(kb+7), k22 = __ldg(kb+8);
    __syncthreads();

    float sr = 0.f, sf = 0.f;
    for (int ry = threadIdx.y; ry < TILE; ry += 8) {
        for (int rx = threadIdx.x; rx < TILE; rx += 32) {
            int ly = ry + 1, lx = rx + 1;
            const float* c = &xt[ly*68 + lx];
            float ax = k00*c[-69] + k01*c[-68] + k02*c[-67]
                     + k10*c[-1]  + k11*c[0]   + k12*c[1]
                     + k20*c[67]  + k21*c[68]  + k22*c[69];
            float fv = fb[(gy0v+ly)*N + (gx0v+lx)];
            float r = fv - ax;
            sr = fmaf(r, r, sr);
            sf = fmaf(fv, fv, sf);
        }
    }
    #pragma unroll
    for (int o = 16; o; o >>= 1) {
        sr += __shfl_down_sync(0xffffffffu, sr, o);
        sf += __shfl_down_sync(0xffffffffu, sf, o);
    }
    if (threadIdx.x == 0) { redbuf[threadIdx.y] = sr; redbuf[8+threadIdx.y] = sf; }
    __syncthreads();
    if (tid == 0) {
        float a = 0.f, bb = 0.f;
        #pragma unroll
        for (int i = 0; i < 8; ++i) { a += redbuf[i]; bb += redbuf[8+i]; }
        atomicAdd(&g_acc[0], (double)a);
        atomicAdd(&g_acc[1], (double)bb);
    }
}

__global__ void finalize_kernel(float* out) {
    out[0] = (float)sqrt(g_acc[0] / g_acc[1]);
}

extern "C" void kernel_launch(void* const* d_in, const int* in_sizes, int n_in,
                              void* d_out, int out_size)
{
    // metadata order: f, kernelA, u(unused), W1, b1, W2, b2, epoch(=201 -> K=3)
    const float* f  = (const float*)d_in[0];
    const float* kA = (const float*)d_in[1];
    const float* W1 = (const float*)d_in[3];
    const float* b1 = (const float*)d_in[4];
    const float* W2 = (const float*)d_in[5];
    const float* b2 = (const float*)d_in[6];
    float* out = (float*)d_out;

    cudaFuncSetAttribute(iter_kernel, cudaFuncAttributeMaxDynamicSharedMemorySize, SMEM_BYTES);

    dim3 grid(N/TILE, N/TILE, BSZ);   // (8, 8, 16)
    dim3 blk(32, 8);

    zero_acc_kernel<<<1, 32>>>();
    // K = 3 outer cycles; x ping-pongs g_x0 <-> g_x1 (starts at zero)
    iter_kernel<<<grid, blk, SMEM_BYTES>>>(0, 1, f, kA, W1, b1, W2, b2); // 0 -> x1
    iter_kernel<<<grid, blk, SMEM_BYTES>>>(1, 0, f, kA, W1, b1, W2, b2); // x1 -> x0
    iter_kernel<<<grid, blk, SMEM_BYTES>>>(0, 0, f, kA, W1, b1, W2, b2); // x0 -> x1
    reduce_kernel<<<grid, blk>>>(f, kA);
    finalize_kernel<<<1, 1>>>(out);
}

// round 2
// speedup vs baseline: 1.3299x; 1.3299x over previous
#include <cuda_runtime.h>
#include <math.h>

#define BSZ  16
#define N    512
#define TILE 64
#define HALO 11
#define RG   (TILE + 2*HALO)   /* 86 */
#define RP   (RG + 2)          /* 88: smem pitch (even -> float2 friendly) */
#define HID  32
#define NPTS (BSZ*N*N)
#define SMEM_BYTES ((2 + 3*RG*RP)*4)   /* 2-float front pad + x ping/pong + f */

typedef unsigned long long ull;

__device__ float  g_x0[NPTS];
__device__ float  g_x1[NPTS];
__device__ double g_acc[2];

__global__ void zero_acc_kernel() {
    if (threadIdx.x < 2) g_acc[threadIdx.x] = 0.0;
}

__device__ __forceinline__ ull pk(float a, float b) {
    ull r; asm("mov.b64 %0,{%1,%2};" : "=l"(r) : "f"(a), "f"(b)); return r;
}
__device__ __forceinline__ void upk(ull v, float& a, float& b) {
    asm("mov.b64 {%0,%1},%2;" : "=f"(a), "=f"(b) : "l"(v));
}
__device__ __forceinline__ ull fma2(ull a, ull b, ull c) {
    ull d; asm("fma.rn.f32x2 %0,%1,%2,%3;" : "=l"(d) : "l"(a), "l"(b), "l"(c)); return d;
}
__device__ __forceinline__ ull mul2(ull a, ull b) {
    ull d; asm("mul.rn.f32x2 %0,%1,%2;" : "=l"(d) : "l"(a), "l"(b)); return d;
}
__device__ __forceinline__ ull add2(ull a, ull b) {
    ull d; asm("add.rn.f32x2 %0,%1,%2;" : "=l"(d) : "l"(a), "l"(b)); return d;
}
__device__ __forceinline__ float tanh_ap(float x) {
    float y; asm("tanh.approx.f32 %0,%1;" : "=f"(y) : "f"(x)); return y;
}
__device__ __forceinline__ float sqrt_ap(float x) {
    float y; asm("sqrt.approx.f32 %0,%1;" : "=f"(y) : "f"(x)); return y;
}

__global__ void __launch_bounds__(256, 2)
iter_kernel(int dir, int zero_in,
            const float* __restrict__ f,  const float* __restrict__ kA,
            const float* __restrict__ W1, const float* __restrict__ b1g,
            const float* __restrict__ W2, const float* __restrict__ b2g)
{
    const float* xin  = dir ? g_x1 : g_x0;
    float*       xout = dir ? g_x0 : g_x1;

    extern __shared__ float smraw[];
    float* xsA = smraw + 2;          // front pad: window may read [-2]
    float* xsB = xsA + RG*RP;
    float* fs  = xsB + RG*RP;

    __shared__ ull sWa[HID], sWb[HID], sBb[HID], sWo[HID];
    __shared__ float ssb2;

    const int b  = blockIdx.z;
    const int tx = threadIdx.x, ty = threadIdx.y;   // 16 x 16
    const int tid = ty*16 + tx;
    const int gx0v = blockIdx.x * TILE - HALO;
    const int gy0v = blockIdx.y * TILE - HALO;

    const float* kb = kA + b * 9;
    const float k00 = __ldg(kb+0), k01 = __ldg(kb+1), k02 = __ldg(kb+2);
    const float k10 = __ldg(kb+3), k11 = __ldg(kb+4), k12 = __ldg(kb+5);
    const float k20 = __ldg(kb+6), k21 = __ldg(kb+7), k22 = __ldg(kb+8);
    const float tau = 0.5f / k11;
    const float nk00=-k00, nk01=-k01, nk02=-k02;
    const float nk10=-k10, nk11=-k11, nk12=-k12;
    const float nk20=-k20, nk21=-k21, nk22=-k22;

    if (tid < HID) {
        float wa = W1[2*tid], wb = W1[2*tid+1], bv = b1g[tid], wo = 0.5f*W2[tid];
        sWa[tid] = pk(wa,wa); sWb[tid] = pk(wb,wb);
        sBb[tid] = pk(bv,bv); sWo[tid] = pk(wo,wo);
    } else if (tid == HID) ssb2 = b2g[0];

    // ---- cooperative region load (zero-padded outside domain); zero pong buffer ----
    const float* fb = f   + b * N * N;
    const float* xb = xin + b * N * N;
    for (int idx = tid; idx < RG*RG; idx += 256) {
        int ly = idx / RG, lx = idx - ly * RG;
        int gy = gy0v + ly, gx = gx0v + lx;
        float xv = 0.f, fv = 0.f;
        if ((unsigned)gx < N && (unsigned)gy < N) {
            int gi = gy * N + gx;
            fv = fb[gi];
            if (!zero_in) xv = xb[gi];
        }
        xsA[ly*RP + lx] = xv;
        fs [ly*RP + lx] = fv;
    }
    for (int idx = tid; idx < RG*RP; idx += 256) xsB[idx] = 0.f;
    __syncthreads();

    // ---- 10 Jacobi sweeps: shrinking region clamped to domain, 2 pts/thread (float2) ----
    float* cur = xsA;
    float* nxt = xsB;
    #pragma unroll 1
    for (int s = 0; s < 10; ++s) {
        const int lo = s + 1, hi = RG - 1 - s;
        const int xlo = max(lo, -gx0v), xhi = min(hi, N - gx0v);
        const int ylo = max(lo, -gy0v), yhi = min(hi, N - gy0v);
        const int px0 = xlo & ~1;
        const int np  = (xhi - px0 + 1) >> 1;
        const int chunk = (yhi - ylo + 15) >> 4;
        const int ys = ylo + ty * chunk;
        const int ye = min(yhi, ys + chunk);
        if (ys < ye) {
            for (int ip = tx; ip < np; ip += 16) {
                const int px = px0 + 2*ip;
                const float o0 = ((unsigned)(gx0v + px)     < (unsigned)N) ? 1.f : 0.f;
                const float o1 = ((unsigned)(gx0v + px + 1) < (unsigned)N) ? 1.f : 0.f;
                const float* rp0 = &cur[(ys-1)*RP + px];
                float ta,tb,tc,td, ma,mb,mc,md;
                { float2 L = *(const float2*)(rp0-2), M = *(const float2*)rp0, R = *(const float2*)(rp0+2);
                  ta=L.y; tb=M.x; tc=M.y; td=R.x; }
                { const float* q = rp0 + RP;
                  float2 L = *(const float2*)(q-2), M = *(const float2*)q, R = *(const float2*)(q+2);
                  ma=L.y; mb=M.x; mc=M.y; md=R.x; }
                const float* rp = rp0 + 2*RP;
                const float* fp = &fs[ys*RP + px];
                float* wp = &nxt[ys*RP + px];
                for (int y = ys; y < ye; ++y) {
                    float2 L = *(const float2*)(rp-2), M = *(const float2*)rp, R = *(const float2*)(rp+2);
                    float na=L.y, nb=M.x, nc=M.y, nd=R.x;
                    float2 fv = *(const float2*)fp;
                    float a0 = fv.x, a1 = fv.y;
                    a0 = fmaf(nk00,ta,a0);  a1 = fmaf(nk00,tb,a1);
                    a0 = fmaf(nk01,tb,a0);  a1 = fmaf(nk01,tc,a1);
                    a0 = fmaf(nk02,tc,a0);  a1 = fmaf(nk02,td,a1);
                    a0 = fmaf(nk10,ma,a0);  a1 = fmaf(nk10,mb,a1);
                    a0 = fmaf(nk11,mb,a0);  a1 = fmaf(nk11,mc,a1);
                    a0 = fmaf(nk12,mc,a0);  a1 = fmaf(nk12,md,a1);
                    a0 = fmaf(nk20,na,a0);  a1 = fmaf(nk20,nb,a1);
                    a0 = fmaf(nk21,nb,a0);  a1 = fmaf(nk21,nc,a1);
                    a0 = fmaf(nk22,nc,a0);  a1 = fmaf(nk22,nd,a1);
                    float2 o;
                    o.x = fmaf(tau, a0, mb) * o0;
                    o.y = fmaf(tau, a1, mc) * o1;
                    *(float2*)wp = o;
                    ta=ma; tb=mb; tc=mc; td=md;
                    ma=na; mb=nb; mc=nc; md=nd;
                    rp += RP; fp += RP; wp += RP;
                }
            }
        }
        __syncthreads();
        float* t = cur; cur = nxt; nxt = t;
    }
    // cur == xsA: x after 10 sweeps, valid on [10,76)^2

    // ---- residual + LFA + packed-f32x2 MLP + global write ----
    const float w2pih = 6.28318530717958647692f / 513.0f;
    const float cA = k00 + k22, cB = k02 + k20, cC = k01 + k21, cD = k10 + k12;
    const float sA = k22 - k00, sB = k02 - k20, sC = k21 - k01, sD = k12 - k10;
    float* xo = xout + b * N * N;

    const int ys_e = HALO + ty * 4;
    float s2a[4], c2a[4];
    #pragma unroll
    for (int i = 0; i < 4; ++i)
        __sincosf(w2pih * (float)(gy0v + ys_e + i - 256), &s2a[i], &c2a[i]);

    const ull K1 = pk(0.03567740814f, 0.03567740814f);
    const ull K0 = pk(0.7978845608f,  0.7978845608f);

    #pragma unroll 1
    for (int g = 0; g < 4; g += 2) {
        ull Rr[4], LF[4];
        float xold[8];
        #pragma unroll
        for (int h = 0; h < 2; ++h) {
            const int cx = HALO + tx + (g+h)*16;
            const int gx = gx0v + cx;
            float s1, c1;
            __sincosf(w2pih * (float)(gx - 256), &s1, &c1);
            const float* rp0 = &cur[(ys_e-1)*RP + cx];
            float t0 = rp0[-1],   t1 = rp0[0],  t2 = rp0[1];
            float m0 = rp0[RP-1], m1 = rp0[RP], m2 = rp0[RP+1];
            float rl[4], ll[4];
            #pragma unroll
            for (int i = 0; i < 4; ++i) {
                const float* nn = rp0 + (i+2)*RP;
                float n0 = nn[-1], n1 = nn[0], n2 = nn[1];
                float acc = fs[(ys_e+i)*RP + cx];
                acc = fmaf(nk00,t0,acc); acc = fmaf(nk01,t1,acc); acc = fmaf(nk02,t2,acc);
                acc = fmaf(nk10,m0,acc); acc = fmaf(nk11,m1,acc); acc = fmaf(nk12,m2,acc);
                acc = fmaf(nk20,n0,acc); acc = fmaf(nk21,n1,acc); acc = fmaf(nk22,n2,acc);
                rl[i] = acc;
                xold[h*4+i] = m1;
                float ssv = s1*s2a[i], cc = c1*c2a[i], sc = s1*c2a[i], cs = c1*s2a[i];
                float cpp = cc - ssv, spp = sc + cs;
                float cpm = cc + ssv, spm = sc - cs;
                float ReS = cA*cpp + cB*cpm + cC*c2a[i] + cD*c1 + k11;
                float ImS = sA*spp + sB*spm + sC*s2a[i] + sD*s1;
                float Re = fmaf(-tau, ReS, 1.f);
                float Im = -tau * ImS;
                float mg2 = fmaf(Re, Re, Im*Im);
                ll[i] = mg2 * mg2 * sqrt_ap(mg2);   // |1-tau*S|^5
                t0=m0; t1=m1; t2=m2;
                m0=n0; m1=n1; m2=n2;
            }
            Rr[h*2+0] = pk(rl[0], rl[1]); Rr[h*2+1] = pk(rl[2], rl[3]);
            LF[h*2+0] = pk(ll[0], ll[1]); LF[h*2+1] = pk(ll[2], ll[3]);
        }
        ull acc2[4], accu[4];
        const ull Z = pk(0.f, 0.f);
        #pragma unroll
        for (int p = 0; p < 4; ++p) { acc2[p] = Z; accu[p] = Z; }
        #pragma unroll 4
        for (int j = 0; j < HID; ++j) {
            const ull wa = sWa[j], wb = sWb[j], bb = sBb[j], wo = sWo[j];
            #pragma unroll
            for (int p = 0; p < 4; ++p) {
                ull v  = fma2(wa, LF[p], fma2(wb, Rr[p], bb));
                ull v2 = mul2(v, v);
                ull q  = fma2(v2, K1, K0);
                ull t  = mul2(v, q);
                float tl, th; upk(t, tl, th);
                ull T  = pk(tanh_ap(tl), tanh_ap(th));
                ull u  = mul2(v, wo);
                acc2[p] = fma2(u, T, acc2[p]);
                accu[p] = add2(accu[p], u);
            }
        }
        #pragma unroll
        for (int h = 0; h < 2; ++h) {
            const int gx = gx0v + HALO + tx + (g+h)*16;
            #pragma unroll
            for (int pp = 0; pp < 2; ++pp) {
                float e0,e1,u0,u1;
                upk(acc2[h*2+pp], e0, e1);
                upk(accu[h*2+pp], u0, u1);
                xo[(gy0v + ys_e + pp*2    )*N + gx] = xold[h*4 + pp*2    ] + ssb2 + e0 + u0;
                xo[(gy0v + ys_e + pp*2 + 1)*N + gx] = xold[h*4 + pp*2 + 1] + ssb2 + e1 + u1;
            }
        }
    }
}

__global__ void __launch_bounds__(256)
reduce_kernel(const float* __restrict__ f, const float* __restrict__ kA)
{
    __shared__ float xt[(TILE+2)*(TILE+4)];   // 66 x 68 pitch
    __shared__ float redbuf[16];
    const int b   = blockIdx.z;
    const int tid = threadIdx.y*32 + threadIdx.x;
    const float* xb = g_x1 + b*N*N;           // final x lives in g_x1
    const float* fb = f    + b*N*N;
    const int gx0v = blockIdx.x*TILE - 1;
    const int gy0v = blockIdx.y*TILE - 1;

    for (int idx = tid; idx < 66*66; idx += 256) {
        int ly = idx / 66, lx = idx - ly*66;
        int gy = gy0v + ly, gx = gx0v + lx;
        xt[ly*68 + lx] = ((unsigned)gx < N && (unsigned)gy < N) ? xb[gy*N + gx] : 0.f;
    }
    const float* kb = kA + b * 9;
    const float k00 = __ldg(kb+0), k01 = __ldg(kb+1), k02 = __ldg(kb+2);
    const float k10 = __ldg(kb+3), k11 = __ldg(kb+4), k12 = __ldg(kb+5);
    const float k20 = __ldg(kb+6), k21 = __ldg(kb+7), k22 = __ldg(kb+8);
    __syncthreads();

    float sr = 0.f, sf = 0.f;
    for (int ry = threadIdx.y; ry < TILE; ry += 8) {
        for (int rx = threadIdx.x; rx < TILE; rx += 32) {
            int ly = ry + 1, lx = rx + 1;
            const float* c = &xt[ly*68 + lx];
            float ax = k00*c[-69] + k01*c[-68] + k02*c[-67]
                     + k10*c[-1]  + k11*c[0]   + k12*c[1]
                     + k20*c[67]  + k21*c[68]  + k22*c[69];
            float fv = fb[(gy0v+ly)*N + (gx0v+lx)];
            float r = fv - ax;
            sr = fmaf(r, r, sr);
            sf = fmaf(fv, fv, sf);
        }
    }
    #pragma unroll
    for (int o = 16; o; o >>= 1) {
        sr += __shfl_down_sync(0xffffffffu, sr, o);
        sf += __shfl_down_sync(0xffffffffu, sf, o);
    }
    if (threadIdx.x == 0) { redbuf[threadIdx.y] = sr; redbuf[8+threadIdx.y] = sf; }
    __syncthreads();
    if (tid == 0) {
        float a = 0.f, bb = 0.f;
        #pragma unroll
        for (int i = 0; i < 8; ++i) { a += redbuf[i]; bb += redbuf[8+i]; }
        atomicAdd(&g_acc[0], (double)a);
        atomicAdd(&g_acc[1], (double)bb);
    }
}

__global__ void finalize_kernel(float* out) {
    out[0] = (float)sqrt(g_acc[0] / g_acc[1]);
}

extern "C" void kernel_launch(void* const* d_in, const int* in_sizes, int n_in,
                              void* d_out, int out_size)
{
    // metadata order: f, kernelA, u(unused), W1, b1, W2, b2, epoch(=201 -> K=3)
    const float* f  = (const float*)d_in[0];
    const float* kA = (const float*)d_in[1];
    const float* W1 = (const float*)d_in[3];
    const float* b1 = (const float*)d_in[4];
    const float* W2 = (const float*)d_in[5];
    const float* b2 = (const float*)d_in[6];
    float* out = (float*)d_out;

    cudaFuncSetAttribute(iter_kernel, cudaFuncAttributeMaxDynamicSharedMemorySize, SMEM_BYTES);

    dim3 grid(N/TILE, N/TILE, BSZ);   // (8, 8, 16)
    dim3 blk(16, 16);
    dim3 blkR(32, 8);

    zero_acc_kernel<<<1, 32>>>();
    // K = 3 outer cycles; x ping-pongs g_x0 <-> g_x1 (starts at zero)
    iter_kernel<<<grid, blk, SMEM_BYTES>>>(0, 1, f, kA, W1, b1, W2, b2); // 0 -> x1
    iter_kernel<<<grid, blk, SMEM_BYTES>>>(1, 0, f, kA, W1, b1, W2, b2); // x1 -> x0
    iter_kernel<<<grid, blk, SMEM_BYTES>>>(0, 0, f, kA, W1, b1, W2, b2); // x0 -> x1
    reduce_kernel<<<grid, blkR>>>(f, kA);
    finalize_kernel<<<1, 1>>>(out);
}

// round 3
// speedup vs baseline: 1.3593x; 1.0222x over previous
#include <cuda_runtime.h>
#include <math.h>

#define BSZ  16
#define N    512
#define TILE 64
#define HALO 11
#define RG   (TILE + 2*HALO)   /* 86 */
#define RP   (RG + 2)          /* 88: smem pitch (even -> 8B friendly) */
#define HID  32
#define NPTS (BSZ*N*N)
#define SMEM_BYTES ((2 + 3*RG*RP)*4)   /* 2-float front pad + x ping/pong + f */

typedef unsigned long long ull;

__device__ float  g_x0[NPTS];
__device__ float  g_x1[NPTS];
__device__ double g_acc[2];

__global__ void zero_acc_kernel() {
    if (threadIdx.x < 2) g_acc[threadIdx.x] = 0.0;
}

__device__ __forceinline__ ull pk(float a, float b) {
    ull r; asm("mov.b64 %0,{%1,%2};" : "=l"(r) : "f"(a), "f"(b)); return r;
}
__device__ __forceinline__ void upk(ull v, float& a, float& b) {
    asm("mov.b64 {%0,%1},%2;" : "=f"(a), "=f"(b) : "l"(v));
}
__device__ __forceinline__ float lo32(ull v) {
    float a, b; upk(v, a, b); return a;
}
__device__ __forceinline__ float hi32(ull v) {
    float a, b; upk(v, a, b); return b;
}
__device__ __forceinline__ ull fma2(ull a, ull b, ull c) {
    ull d; asm("fma.rn.f32x2 %0,%1,%2,%3;" : "=l"(d) : "l"(a), "l"(b), "l"(c)); return d;
}
__device__ __forceinline__ ull mul2(ull a, ull b) {
    ull d; asm("mul.rn.f32x2 %0,%1,%2;" : "=l"(d) : "l"(a), "l"(b)); return d;
}
__device__ __forceinline__ ull add2(ull a, ull b) {
    ull d; asm("add.rn.f32x2 %0,%1,%2;" : "=l"(d) : "l"(a), "l"(b)); return d;
}
__device__ __forceinline__ float tanh_ap(float x) {
    float y; asm("tanh.approx.f32 %0,%1;" : "=f"(y) : "f"(x)); return y;
}
__device__ __forceinline__ float sqrt_ap(float x) {
    float y; asm("sqrt.approx.f32 %0,%1;" : "=f"(y) : "f"(x)); return y;
}

__global__ void __launch_bounds__(256, 2)
iter_kernel(int dir, int zero_in,
            const float* __restrict__ f,  const float* __restrict__ kA,
            const float* __restrict__ W1, const float* __restrict__ b1g,
            const float* __restrict__ W2, const float* __restrict__ b2g)
{
    const float* xin  = dir ? g_x1 : g_x0;
    float*       xout = dir ? g_x0 : g_x1;

    extern __shared__ float smraw[];
    float* xsA = smraw + 2;          // front pad: window may read [-2]
    float* xsB = xsA + RG*RP;
    float* fs  = xsB + RG*RP;

    __shared__ ull sWa[HID], sWb[HID], sBb[HID], sWo[HID];
    __shared__ float ssb2;

    const int b  = blockIdx.z;
    const int tx = threadIdx.x, ty = threadIdx.y;   // 16 x 16
    const int tid = ty*16 + tx;
    const int gx0v = blockIdx.x * TILE - HALO;
    const int gy0v = blockIdx.y * TILE - HALO;

    const float* kb = kA + b * 9;
    const float k00 = __ldg(kb+0), k01 = __ldg(kb+1), k02 = __ldg(kb+2);
    const float k10 = __ldg(kb+3), k11 = __ldg(kb+4), k12 = __ldg(kb+5);
    const float k20 = __ldg(kb+6), k21 = __ldg(kb+7), k22 = __ldg(kb+8);
    const float tau = 0.5f / k11;
    const float nk00=-k00, nk01=-k01, nk02=-k02;
    const float nk10=-k10, nk11=-k11, nk12=-k12;
    const float nk20=-k20, nk21=-k21, nk22=-k22;
    // packed (duplicated) negated coefficients for f32x2 stencil
    const ull P00 = pk(nk00,nk00), P01 = pk(nk01,nk01), P02 = pk(nk02,nk02);
    const ull P10 = pk(nk10,nk10), P11 = pk(nk11,nk11), P12 = pk(nk12,nk12);
    const ull P20 = pk(nk20,nk20), P21 = pk(nk21,nk21), P22 = pk(nk22,nk22);
    const ull TAUP = pk(tau, tau);

    if (tid < HID) {
        float wa = W1[2*tid], wb = W1[2*tid+1], bv = b1g[tid], wo = 0.5f*W2[tid];
        sWa[tid] = pk(wa,wa); sWb[tid] = pk(wb,wb);
        sBb[tid] = pk(bv,bv); sWo[tid] = pk(wo,wo);
    } else if (tid == HID) ssb2 = b2g[0];

    // ---- cooperative region load (zero-padded outside domain); zero pong buffer ----
    // zero_in: fold the first Jacobi sweep into the load: x1 = tau * f
    const float* fb = f   + b * N * N;
    const float* xb = xin + b * N * N;
    for (int idx = tid; idx < RG*RG; idx += 256) {
        int ly = idx / RG, lx = idx - ly * RG;
        int gy = gy0v + ly, gx = gx0v + lx;
        float xv = 0.f, fv = 0.f;
        if ((unsigned)gx < N && (unsigned)gy < N) {
            int gi = gy * N + gx;
            fv = fb[gi];
            xv = zero_in ? (tau * fv) : xb[gi];
        }
        xsA[ly*RP + lx] = xv;
        fs [ly*RP + lx] = fv;
    }
    for (int idx = tid; idx < RG*RP; idx += 256) xsB[idx] = 0.f;
    __syncthreads();

    // ---- Jacobi sweeps (packed f32x2): shrinking region clamped to domain ----
    float* cur = xsA;
    float* nxt = xsB;
    const int s0 = zero_in ? 1 : 0;   // zero_in did sweep "0" at load (full-region valid)
    #pragma unroll 1
    for (int s = s0; s < 10; ++s) {
        const int lo = s + 1, hi = RG - 1 - s;
        const int xlo = max(lo, -gx0v), xhi = min(hi, N - gx0v);
        const int ylo = max(lo, -gy0v), yhi = min(hi, N - gy0v);
        const int px0 = xlo & ~1;
        const int np  = (xhi - px0 + 1) >> 1;
        const int chunk = (yhi - ylo + 15) >> 4;
        const int ys = ylo + ty * chunk;
        const int ye = min(yhi, ys + chunk);
        if (ys < ye) {
            for (int ip = tx; ip < np; ip += 16) {
                const int px = px0 + 2*ip;
                const float o0 = ((unsigned)(gx0v + px)     < (unsigned)N) ? 1.f : 0.f;
                const float o1 = ((unsigned)(gx0v + px + 1) < (unsigned)N) ? 1.f : 0.f;
                const ull MASKP = pk(o0, o1);
                const float* rp = &cur[(ys-1)*RP + px];
                ull Ct = *(const ull*)rp;
                ull Lt = pk(rp[-1], lo32(Ct)), Rt = pk(hi32(Ct), rp[2]);
                rp += RP;
                ull Cm = *(const ull*)rp;
                ull Lm = pk(rp[-1], lo32(Cm)), Rm = pk(hi32(Cm), rp[2]);
                rp += RP;
                const float* fp = &fs[ys*RP + px];
                float* wp = &nxt[ys*RP + px];
                #pragma unroll 2
                for (int y = ys; y < ye; ++y) {
                    ull Cb = *(const ull*)rp;
                    ull Lb = pk(rp[-1], lo32(Cb)), Rb = pk(hi32(Cb), rp[2]);
                    ull acc = *(const ull*)fp;
                    acc = fma2(P00, Lt, acc); acc = fma2(P01, Ct, acc); acc = fma2(P02, Rt, acc);
                    acc = fma2(P10, Lm, acc); acc = fma2(P11, Cm, acc); acc = fma2(P12, Rm, acc);
                    acc = fma2(P20, Lb, acc); acc = fma2(P21, Cb, acc); acc = fma2(P22, Rb, acc);
                    *(ull*)wp = mul2(fma2(TAUP, acc, Cm), MASKP);
                    Lt = Lm; Ct = Cm; Rt = Rm;
                    Lm = Lb; Cm = Cb; Rm = Rb;
                    rp += RP; fp += RP; wp += RP;
                }
            }
        }
        __syncthreads();
        float* t = cur; cur = nxt; nxt = t;
    }
    // cur: x after 10 sweeps, valid on [10,76)^2

    // ---- residual + LFA + packed-f32x2 MLP + global write ----
    const float w2pih = 6.28318530717958647692f / 513.0f;
    const float cA = k00 + k22, cB = k02 + k20, cC = k01 + k21, cD = k10 + k12;
    const float sA = k22 - k00, sB = k02 - k20, sC = k21 - k01, sD = k12 - k10;
    float* xo = xout + b * N * N;

    const int ys_e = HALO + ty * 4;
    float s2a[4], c2a[4];
    #pragma unroll
    for (int i = 0; i < 4; ++i)
        __sincosf(w2pih * (float)(gy0v + ys_e + i - 256), &s2a[i], &c2a[i]);

    const ull K1 = pk(0.03567740814f, 0.03567740814f);
    const ull K0 = pk(0.7978845608f,  0.7978845608f);

    #pragma unroll 1
    for (int g = 0; g < 4; g += 2) {
        ull Rr[4], LF[4];
        float xold[8];
        #pragma unroll
        for (int h = 0; h < 2; ++h) {
            const int cx = HALO + tx + (g+h)*16;
            const int gx = gx0v + cx;
            float s1, c1;
            __sincosf(w2pih * (float)(gx - 256), &s1, &c1);
            const float* rp0 = &cur[(ys_e-1)*RP + cx];
            float t0 = rp0[-1],   t1 = rp0[0],  t2 = rp0[1];
            float m0 = rp0[RP-1], m1 = rp0[RP], m2 = rp0[RP+1];
            float rl[4], ll[4];
            #pragma unroll
            for (int i = 0; i < 4; ++i) {
                const float* nn = rp0 + (i+2)*RP;
                float n0 = nn[-1], n1 = nn[0], n2 = nn[1];
                float acc = fs[(ys_e+i)*RP + cx];
                acc = fmaf(nk00,t0,acc); acc = fmaf(nk01,t1,acc); acc = fmaf(nk02,t2,acc);
                acc = fmaf(nk10,m0,acc); acc = fmaf(nk11,m1,acc); acc = fmaf(nk12,m2,acc);
                acc = fmaf(nk20,n0,acc); acc = fmaf(nk21,n1,acc); acc = fmaf(nk22,n2,acc);
                rl[i] = acc;
                xold[h*4+i] = m1;
                float ssv = s1*s2a[i], cc = c1*c2a[i], sc = s1*c2a[i], cs = c1*s2a[i];
                float cpp = cc - ssv, spp = sc + cs;
                float cpm = cc + ssv, spm = sc - cs;
                float ReS = cA*cpp + cB*cpm + cC*c2a[i] + cD*c1 + k11;
                float ImS = sA*spp + sB*spm + sC*s2a[i] + sD*s1;
                float Re = fmaf(-tau, ReS, 1.f);
                float Im = -tau * ImS;
                float mg2 = fmaf(Re, Re, Im*Im);
                ll[i] = mg2 * mg2 * sqrt_ap(mg2);   // |1-tau*S|^5
                t0=m0; t1=m1; t2=m2;
                m0=n0; m1=n1; m2=n2;
            }
            Rr[h*2+0] = pk(rl[0], rl[1]); Rr[h*2+1] = pk(rl[2], rl[3]);
            LF[h*2+0] = pk(ll[0], ll[1]); LF[h*2+1] = pk(ll[2], ll[3]);
        }
        ull acc2[4], accu[4];
        const ull Z = pk(0.f, 0.f);
        #pragma unroll
        for (int p = 0; p < 4; ++p) { acc2[p] = Z; accu[p] = Z; }
        #pragma unroll 4
        for (int j = 0; j < HID; ++j) {
            const ull wa = sWa[j], wb = sWb[j], bb = sBb[j], wo = sWo[j];
            #pragma unroll
            for (int p = 0; p < 4; ++p) {
                ull v  = fma2(wa, LF[p], fma2(wb, Rr[p], bb));
                ull v2 = mul2(v, v);
                ull q  = fma2(v2, K1, K0);
                ull t  = mul2(v, q);
                float tl, th; upk(t, tl, th);
                ull T  = pk(tanh_ap(tl), tanh_ap(th));
                ull u  = mul2(v, wo);
                acc2[p] = fma2(u, T, acc2[p]);
                accu[p] = add2(accu[p], u);
            }
        }
        #pragma unroll
        for (int h = 0; h < 2; ++h) {
            const int gx = gx0v + HALO + tx + (g+h)*16;
            #pragma unroll
            for (int pp = 0; pp < 2; ++pp) {
                float e0,e1,u0,u1;
                upk(acc2[h*2+pp], e0, e1);
                upk(accu[h*2+pp], u0, u1);
                xo[(gy0v + ys_e + pp*2    )*N + gx] = xold[h*4 + pp*2    ] + ssb2 + e0 + u0;
                xo[(gy0v + ys_e + pp*2 + 1)*N + gx] = xold[h*4 + pp*2 + 1] + ssb2 + e1 + u1;
            }
        }
    }
}

__global__ void __launch_bounds__(256)
reduce_kernel(const float* __restrict__ f, const float* __restrict__ kA)
{
    __shared__ float xt[(TILE+2)*(TILE+4)];   // 66 x 68 pitch
    __shared__ float redbuf[16];
    const int b   = blockIdx.z;
    const int tid = threadIdx.y*32 + threadIdx.x;
    const float* xb = g_x1 + b*N*N;           // final x lives in g_x1
    const float* fb = f    + b*N*N;
    const int gx0v = blockIdx.x*TILE - 1;
    const int gy0v = blockIdx.y*TILE - 1;

    for (int idx = tid; idx < 66*66; idx += 256) {
        int ly = idx / 66, lx = idx - ly*66;
        int gy = gy0v + ly, gx = gx0v + lx;
        xt[ly*68 + lx] = ((unsigned)gx < N && (unsigned)gy < N) ? xb[gy*N + gx] : 0.f;
    }
    const float* kb = kA + b * 9;
    const float k00 = __ldg(kb+0), k01 = __ldg(kb+1), k02 = __ldg(kb+2);
    const float k10 = __ldg(kb+3), k11 = __ldg(kb+4), k12 = __ldg(kb+5);
    const float k20 = __ldg(kb+6), k21 = __ldg(kb+7), k22 = __ldg(kb+8);
    __syncthreads();

    float sr = 0.f, sf = 0.f;
    for (int ry = threadIdx.y; ry < TILE; ry += 8) {
        for (int rx = threadIdx.x; rx < TILE; rx += 32) {
            int ly = ry + 1, lx = rx + 1;
            const float* c = &xt[ly*68 + lx];
            float ax = k00*c[-69] + k01*c[-68] + k02*c[-67]
                     + k10*c[-1]  + k11*c[0]   + k12*c[1]
                     + k20*c[67]  + k21*c[68]  + k22*c[69];
            float fv = fb[(gy0v+ly)*N + (gx0v+lx)];
            float r = fv - ax;
            sr = fmaf(r, r, sr);
            sf = fmaf(fv, fv, sf);
        }
    }
    #pragma unroll
    for (int o = 16; o; o >>= 1) {
        sr += __shfl_down_sync(0xffffffffu, sr, o);
        sf += __shfl_down_sync(0xffffffffu, sf, o);
    }
    if (threadIdx.x == 0) { redbuf[threadIdx.y] = sr; redbuf[8+threadIdx.y] = sf; }
    __syncthreads();
    if (tid == 0) {
        float a = 0.f, bb = 0.f;
        #pragma unroll
        for (int i = 0; i < 8; ++i) { a += redbuf[i]; bb += redbuf[8+i]; }
        atomicAdd(&g_acc[0], (double)a);
        atomicAdd(&g_acc[1], (double)bb);
    }
}

__global__ void finalize_kernel(float* out) {
    out[0] = (float)sqrt(g_acc[0] / g_acc[1]);
}

extern "C" void kernel_launch(void* const* d_in, const int* in_sizes, int n_in,
                              void* d_out, int out_size)
{
    // metadata order: f, kernelA, u(unused), W1, b1, W2, b2, epoch(=201 -> K=3)
    const float* f  = (const float*)d_in[0];
    const float* kA = (const float*)d_in[1];
    const float* W1 = (const float*)d_in[3];
    const float* b1 = (const float*)d_in[4];
    const float* W2 = (const float*)d_in[5];
    const float* b2 = (const float*)d_in[6];
    float* out = (float*)d_out;

    cudaFuncSetAttribute(iter_kernel, cudaFuncAttributeMaxDynamicSharedMemorySize, SMEM_BYTES);

    dim3 grid(N/TILE, N/TILE, BSZ);   // (8, 8, 16)
    dim3 blk(16, 16);
    dim3 blkR(32, 8);

    zero_acc_kernel<<<1, 32>>>();
    // K = 3 outer cycles; x ping-pongs g_x0 <-> g_x1 (starts at zero)
    iter_kernel<<<grid, blk, SMEM_BYTES>>>(0, 1, f, kA, W1, b1, W2, b2); // 0 -> x1
    iter_kernel<<<grid, blk, SMEM_BYTES>>>(1, 0, f, kA, W1, b1, W2, b2); // x1 -> x0
    iter_kernel<<<grid, blk, SMEM_BYTES>>>(0, 0, f, kA, W1, b1, W2, b2); // x0 -> x1
    reduce_kernel<<<grid, blkR>>>(f, kA);
    finalize_kernel<<<1, 1>>>(out);
}